// round 3
// baseline (speedup 1.0000x reference)
#include <cuda_runtime.h>
#include <cuda_bf16.h>
#include <cstdint>

typedef unsigned long long u64;

// Problem constants
#define BATCH 32
#define C     512      // input channels (both inputs)
#define P     196      // 14*14 pixels
#define D     8192     // sketch output dim (power of two)
#define DMASK (D - 1)

// Tiling
#define C1B   128      // c1 rows per CTA
#define C2B   128      // c2 chunk per inner iteration
#define ASTRIDE 196    // As packed (a-loads are broadcast; banks irrelevant; 8B aligned)
#define BSTRIDE 198    // Bs padded: word4 bank = 6*tx mod 32, distinct for tx 0..15
#define NTHREADS 256

// Sketch hash/sign tables extracted from the dense S matrices each launch.
__device__ int   g_h1[C];
__device__ int   g_h2[C];
__device__ float g_s1[C];
__device__ float g_s2[C];

// ---------------------------------------------------------------------------
// Kernel 1: extract (h, s) from dense sketch matrices S[512, 8192] (one +-1
// nonzero per row), AND zero the output buffer (folded in to save a launch).
// grid: (512, 2)  block: 256
// ---------------------------------------------------------------------------
__global__ void cbp_prep(const float* __restrict__ S1, const float* __restrict__ S2,
                         float* __restrict__ out) {
    const int row = blockIdx.x;
    const float4* r = (const float4*)(((blockIdx.y == 0) ? S1 : S2) + (size_t)row * D);
    for (int j4 = threadIdx.x; j4 < D / 4; j4 += blockDim.x) {
        float4 v = r[j4];
        float nz = 0.0f; int off = 0;
        if (v.x != 0.0f) { nz = v.x; off = 0; }
        if (v.y != 0.0f) { nz = v.y; off = 1; }
        if (v.z != 0.0f) { nz = v.z; off = 2; }
        if (v.w != 0.0f) { nz = v.w; off = 3; }
        if (nz != 0.0f) {
            int j = j4 * 4 + off;
            if (blockIdx.y == 0) { g_h1[row] = j; g_s1[row] = nz; }
            else                 { g_h2[row] = j; g_s2[row] = nz; }
        }
    }
    // Zero out[32*8192]: 1024 blocks x 256 floats
    int base = (blockIdx.y * gridDim.x + blockIdx.x) * 256;
    out[base + threadIdx.x] = 0.0f;
}

// ---------------------------------------------------------------------------
// Kernel 2: fused Gram GEMM + count-sketch circular-conv scatter.
// grid: (4, 32)  block: 256 (16x16 logical).
//   c1 = ty + ii*16  (ii 0..7),  c2 = tx + jj*16 (jj 0..7)  -> 128x128 tile
// Inner loop: k in steps of 2; LDS.64 loads give (x[k], x[k+1]) pre-packed for
// fma.rn.f32x2; each u64 accumulator holds (even-k, odd-k) partials; lo+hi at
// the end is the exact fp32 Gram entry.
// Scatter: straight to global via RED.add (L2 atomic ALUs) -- no smem acc.
// Dynamic smem: As[128*196] + Bs[128*198] floats = 201728 bytes
// ---------------------------------------------------------------------------
#define SMEM_FLOATS (C1B * ASTRIDE + C2B * BSTRIDE)
#define SMEM_BYTES  (SMEM_FLOATS * 4)

__global__ void __launch_bounds__(NTHREADS, 1)
cbp_main(const float* __restrict__ B1g, const float* __restrict__ B2g,
         float* __restrict__ out) {
    extern __shared__ float sm[];
    float* As = sm;                    // [C1B][ASTRIDE]
    float* Bs = sm + C1B * ASTRIDE;    // [C2B][BSTRIDE]

    const int b      = blockIdx.y;
    const int c1blk  = blockIdx.x * C1B;
    const int tid    = threadIdx.x;
    const int tx     = tid & 15;
    const int ty     = tid >> 4;

    // Load A tile (128 x 196), sign-folded, float4 gmem reads
    {
        const float* Ag = B1g + ((size_t)b * C + c1blk) * P;
        for (int i = tid; i < C1B * (P / 4); i += NTHREADS) {
            int c  = i / (P / 4);
            int p4 = i % (P / 4);
            float4 v = ((const float4*)(Ag + (size_t)c * P))[p4];
            float  s = g_s1[c1blk + c];
            float* dst = As + c * ASTRIDE + p4 * 4;
            dst[0] = v.x * s; dst[1] = v.y * s; dst[2] = v.z * s; dst[3] = v.w * s;
        }
    }

    const float* aRow = As + ty * ASTRIDE;
    const float* bRow = Bs + tx * BSTRIDE;
    float* outb = out + (size_t)b * D;

    for (int cc = 0; cc < C / C2B; cc++) {
        __syncthreads();  // previous iteration's compute done reading Bs
        // Load B chunk (128 x 196), sign-folded
        {
            const float* Bg = B2g + ((size_t)b * C + cc * C2B) * P;
            for (int i = tid; i < C2B * (P / 4); i += NTHREADS) {
                int c  = i / (P / 4);
                int p4 = i % (P / 4);
                float4 v = ((const float4*)(Bg + (size_t)c * P))[p4];
                float  s = g_s2[cc * C2B + c];
                float* dst = Bs + c * BSTRIDE + p4 * 4;
                dst[0] = v.x * s; dst[1] = v.y * s; dst[2] = v.z * s; dst[3] = v.w * s;
            }
        }
        __syncthreads();  // tiles ready (covers A load on cc==0)

        // ---- 128x128 Gram tile: 8x8 microtile, packed (even-k, odd-k) FMAs ----
        u64 accp[8][8];
        #pragma unroll
        for (int ii = 0; ii < 8; ii++)
            #pragma unroll
            for (int jj = 0; jj < 8; jj++) accp[ii][jj] = 0ull;

        #pragma unroll 2
        for (int k = 0; k < P; k += 2) {
            u64 aq[8], bq[8];
            #pragma unroll
            for (int ii = 0; ii < 8; ii++)
                aq[ii] = *(const u64*)(aRow + ii * 16 * ASTRIDE + k);
            #pragma unroll
            for (int jj = 0; jj < 8; jj++)
                bq[jj] = *(const u64*)(bRow + jj * 16 * BSTRIDE + k);
            #pragma unroll
            for (int ii = 0; ii < 8; ii++)
                #pragma unroll
                for (int jj = 0; jj < 8; jj++)
                    asm("fma.rn.f32x2 %0, %1, %2, %0;"
                        : "+l"(accp[ii][jj]) : "l"(aq[ii]), "l"(bq[jj]));
        }

        // ---- Scatter tile straight to global bins via RED.add ----
        int h2v[8];
        #pragma unroll
        for (int jj = 0; jj < 8; jj++)
            h2v[jj] = __ldg(g_h2 + cc * C2B + tx + jj * 16);

        #pragma unroll
        for (int ii = 0; ii < 8; ii++) {
            int h1v = __ldg(g_h1 + c1blk + ty + ii * 16);
            #pragma unroll
            for (int jj = 0; jj < 8; jj++) {
                unsigned int lo_u, hi_u;
                asm("mov.b64 {%0,%1}, %2;" : "=r"(lo_u), "=r"(hi_u) : "l"(accp[ii][jj]));
                float v = __uint_as_float(lo_u) + __uint_as_float(hi_u);
                atomicAdd(outb + ((h1v + h2v[jj]) & DMASK), v);
            }
        }
    }
}

// ---------------------------------------------------------------------------
// Harness entry
// Inputs (metadata order): bottom1 [32,512,14,14] f32, bottom2 [32,512,14,14] f32,
//                          S1 [512,8192] f32, S2 [512,8192] f32
// Output: [32, 8192] f32
// ---------------------------------------------------------------------------
extern "C" void kernel_launch(void* const* d_in, const int* in_sizes, int n_in,
                              void* d_out, int out_size) {
    const float* b1 = (const float*)d_in[0];
    const float* b2 = (const float*)d_in[1];
    const float* S1 = (const float*)d_in[2];
    const float* S2 = (const float*)d_in[3];
    float* out = (float*)d_out;

    cudaFuncSetAttribute(cbp_main, cudaFuncAttributeMaxDynamicSharedMemorySize,
                         SMEM_BYTES);

    cbp_prep<<<dim3(C, 2), 256>>>(S1, S2, out);
    cbp_main<<<dim3(C / C1B, BATCH), NTHREADS, SMEM_BYTES>>>(b1, b2, out);
}